// round 15
// baseline (speedup 1.0000x reference)
#include <cuda_runtime.h>
#include <cuda_fp16.h>
#include <cstdint>
#include <math.h>

// Problem constants
#define Bc 2
#define Tc 2048
#define Ec 2048
#define Hc 16
#define Dc 64
#define MTOT (Bc * Tc)  // 4096

// ---------------------------------------------------------------------------
// Device scratch (no allocations allowed)
// ---------------------------------------------------------------------------
__device__ __half g_Q[Bc * Tc * Ec];                      // fp16, pre-scaled
__device__ __half g_K[Bc * Tc * Ec];                      // fp16
__device__ __half g_V[Bc * Tc * Ec];                      // fp16
__device__ float  g_O[(size_t)Bc * 2 * Hc * Tc * 2 * Dc]; // [B, 2H, T, 128] fp32
__device__ __half g_ctx[Bc * Tc * Ec];                    // fp16
__device__ __half g_Xh[MTOT * Ec];                        // fp16 query
__device__ __half g_Wh[4 * Ec * Ec];                      // fp16 weights (q,k,v,o)
__device__ float  g_lam;

// ---------------------------------------------------------------------------
// PTX helpers
// ---------------------------------------------------------------------------
__device__ __forceinline__ uint32_t smem_u32(const void* p) {
    uint32_t a;
    asm("{ .reg .u64 t; cvta.to.shared.u64 t, %1; cvt.u32.u64 %0, t; }" : "=r"(a) : "l"(p));
    return a;
}
__device__ __forceinline__ void cpa16(uint32_t saddr, const void* g) {
    asm volatile("cp.async.cg.shared.global [%0], [%1], 16;" :: "r"(saddr), "l"(g));
}
#define CP_COMMIT() asm volatile("cp.async.commit_group;" ::: "memory")
#define CP_WAIT(n) asm volatile("cp.async.wait_group %0;" :: "n"(n) : "memory")

__device__ __forceinline__ void mma_f16(float* d, const uint32_t* a, const uint32_t* b) {
    asm volatile(
        "mma.sync.aligned.m16n8k16.row.col.f32.f16.f16.f32 "
        "{%0,%1,%2,%3}, {%4,%5,%6,%7}, {%8,%9}, {%0,%1,%2,%3};"
        : "+f"(d[0]), "+f"(d[1]), "+f"(d[2]), "+f"(d[3])
        : "r"(a[0]), "r"(a[1]), "r"(a[2]), "r"(a[3]), "r"(b[0]), "r"(b[1]));
}
#define LDSM_X4(r, addr) \
    asm volatile("ldmatrix.sync.aligned.m8n8.x4.shared.b16 {%0,%1,%2,%3}, [%4];" \
                 : "=r"((r)[0]), "=r"((r)[1]), "=r"((r)[2]), "=r"((r)[3]) : "r"(addr))
#define LDSM_X4_T(r, addr) \
    asm volatile("ldmatrix.sync.aligned.m8n8.x4.trans.shared.b16 {%0,%1,%2,%3}, [%4];" \
                 : "=r"((r)[0]), "=r"((r)[1]), "=r"((r)[2]), "=r"((r)[3]) : "r"(addr))

__device__ __forceinline__ uint32_t pack_h2(float lo, float hi) {
    __half2 h = __floats2half2_rn(lo, hi);
    return *(uint32_t*)&h;
}

// ---------------------------------------------------------------------------
// fp32 -> fp16 convert (1:1)
// ---------------------------------------------------------------------------
__global__ __launch_bounds__(256) void cvt_f2h_kernel(
    const float* __restrict__ in, __half* __restrict__ out, int n4)
{
    const int i = blockIdx.x * 256 + threadIdx.x;
    if (i < n4) {
        float4 v = *(const float4*)(in + 4 * (size_t)i);
        __half2* o = (__half2*)(out + 4 * (size_t)i);
        o[0] = __floats2half2_rn(v.x, v.y);
        o[1] = __floats2half2_rn(v.z, v.w);
    }
}

// All four weights in one launch (grid.y selects weight)
__global__ __launch_bounds__(256) void cvt_w4_kernel(
    const float* __restrict__ w0, const float* __restrict__ w1,
    const float* __restrict__ w2, const float* __restrict__ w3,
    __half* __restrict__ out)
{
    const int y = blockIdx.y;
    const float* src = (y == 0) ? w0 : (y == 1) ? w1 : (y == 2) ? w2 : w3;
    const int i = blockIdx.x * 256 + threadIdx.x;
    float4 v = *(const float4*)(src + 4 * (size_t)i);
    __half2* o = (__half2*)(out + (size_t)y * Ec * Ec + 4 * (size_t)i);
    o[0] = __floats2half2_rn(v.x, v.y);
    o[1] = __floats2half2_rn(v.z, v.w);
}

// ---------------------------------------------------------------------------
// GEMM (R12-proven): CTA 128x128, 4 warps (2x2), warp tile 64x64.
// 3-stage cp.async (CP_WAIT(1)), one barrier per K-tile, natural regs.
// ---------------------------------------------------------------------------
#define BM 128
#define BN 128
#define BK 32
#define HLDA 40
#define STAGE_H (BM * HLDA)                      // 5120 halfs per matrix
#define GSMEM_BYTES (3 * 2 * STAGE_H * 2)        // 61440 B
#define GTHREADS 128

__device__ __forceinline__ void g_stage_load(__half* stage, const __half* __restrict__ X,
                                             const __half* __restrict__ W,
                                             int m0, int n0, int K, int kt, int tid) {
    __half* Ad = stage;
    __half* Bd = stage + STAGE_H;
    const int kcol = kt * BK;
#pragma unroll
    for (int i = 0; i < 4; i++) {
        const int c = tid + GTHREADS * i;     // 0..511
        const int r = c >> 2, sg = c & 3;
        cpa16(smem_u32(Ad + r * HLDA + sg * 8), X + (size_t)(m0 + r) * K + kcol + sg * 8);
        cpa16(smem_u32(Bd + r * HLDA + sg * 8), W + (size_t)(n0 + r) * K + kcol + sg * 8);
    }
    CP_COMMIT();
}

__device__ __forceinline__ void gemm_core(
    const __half* __restrict__ X, const __half* __restrict__ W,
    float* __restrict__ Cf, __half* __restrict__ Ch,
    int m0, int n0, float alpha, int out_half, __half* smem)
{
    const int N = Ec, K = Ec;
    const int tid = threadIdx.x;
    const int wid = tid >> 5;
    const int lane = tid & 31;
    const int g = lane >> 2;
    const int tig = lane & 3;
    const int warp_m = (wid & 1) * 64;
    const int warp_n = (wid >> 1) * 64;
    const int NK = K / BK;

    const uint32_t sb = smem_u32(smem);
    const uint32_t a_off = (uint32_t)(((warp_m + (lane & 15)) * HLDA + (lane >> 4) * 8) * 2);
    const uint32_t b_off = (uint32_t)((STAGE_H + (warp_n + (lane & 7) + ((lane >> 4) << 3)) * HLDA
                                      + ((lane >> 3) & 1) * 8) * 2);

    float acc[4][8][4];
#pragma unroll
    for (int i = 0; i < 4; i++)
#pragma unroll
        for (int j = 0; j < 8; j++)
#pragma unroll
            for (int r = 0; r < 4; r++) acc[i][j][r] = 0.f;

    g_stage_load(smem, X, W, m0, n0, K, 0, tid);
    g_stage_load(smem + 2 * STAGE_H, X, W, m0, n0, K, 1, tid);

    for (int kt = 0; kt < NK; kt++) {
        const int p = kt % 3;
        if (kt + 2 < NK) CP_WAIT(1); else CP_WAIT(0);
        __syncthreads();
        if (kt + 2 < NK)
            g_stage_load(smem + ((kt + 2) % 3) * 2 * STAGE_H, X, W, m0, n0, K, kt + 2, tid);

        const uint32_t stg = sb + (uint32_t)(p * 2 * STAGE_H * 2);
#pragma unroll
        for (int kc = 0; kc < 2; kc++) {
            const uint32_t ko = (uint32_t)(kc * 32);
            uint32_t afr[4][4], bfr[4][4];
#pragma unroll
            for (int i = 0; i < 4; i++)
                LDSM_X4(afr[i], stg + a_off + (uint32_t)(i * 16 * HLDA * 2) + ko);
#pragma unroll
            for (int j2 = 0; j2 < 4; j2++)
                LDSM_X4(bfr[j2], stg + b_off + (uint32_t)(j2 * 16 * HLDA * 2) + ko);
#pragma unroll
            for (int i = 0; i < 4; i++)
#pragma unroll
                for (int j = 0; j < 8; j++)
                    mma_f16(acc[i][j], afr[i], bfr[j >> 1] + (j & 1) * 2);
        }
    }

#pragma unroll
    for (int i = 0; i < 4; i++) {
#pragma unroll
        for (int j = 0; j < 8; j++) {
            const int row = m0 + warp_m + i * 16 + g;
            const int col = n0 + warp_n + j * 8 + 2 * tig;
            const float c0 = acc[i][j][0] * alpha, c1 = acc[i][j][1] * alpha;
            const float c2 = acc[i][j][2] * alpha, c3 = acc[i][j][3] * alpha;
            if (out_half) {
                *(__half2*)(Ch + (size_t)row * N + col) = __floats2half2_rn(c0, c1);
                *(__half2*)(Ch + (size_t)(row + 8) * N + col) = __floats2half2_rn(c2, c3);
            } else {
                *(float2*)(Cf + (size_t)row * N + col) = make_float2(c0, c1);
                *(float2*)(Cf + (size_t)(row + 8) * N + col) = make_float2(c2, c3);
            }
        }
    }
}

// Fused Q/K/V projections: grid.z selects weight/output/alpha.
__global__ __launch_bounds__(GTHREADS) void gemm_qkv(
    const __half* __restrict__ X, const __half* __restrict__ Wb,
    __half* __restrict__ Qo, __half* __restrict__ Ko, __half* __restrict__ Vo)
{
    extern __shared__ __align__(16) __half smem[];
    const int z = blockIdx.z;
    const __half* W = Wb + (size_t)z * Ec * Ec;
    __half* Ch = (z == 0) ? Qo : (z == 1) ? Ko : Vo;
    const float alpha = (z == 0) ? 0.125f : 1.0f;
    gemm_core(X, W, nullptr, Ch, blockIdx.y * BM, blockIdx.x * BN, alpha, 1, smem);
}

// Output projection (fp32 out) — R12-proven 128x128 path.
__global__ __launch_bounds__(GTHREADS) void gemm_wo(
    const __half* __restrict__ X, const __half* __restrict__ W,
    float* __restrict__ Cf)
{
    extern __shared__ __align__(16) __half smem[];
    gemm_core(X, W, Cf, nullptr, blockIdx.y * BM, blockIdx.x * BN, 1.0f, 0, smem);
}

// ---------------------------------------------------------------------------
// Lambda scalar
// ---------------------------------------------------------------------------
__global__ void lambda_kernel(const float* __restrict__ lq1, const float* __restrict__ lk1,
                              const float* __restrict__ lq2, const float* __restrict__ lk2)
{
    float s1 = 0.f, s2 = 0.f;
    for (int i = 0; i < Dc; i++) {
        s1 += lq1[i] * lk1[i];
        s2 += lq2[i] * lk2[i];
    }
    const float LI = 0.8f - 0.6f * expf(-3.6f);
    g_lam = expf(s1) - expf(s2) + LI;
}

// ---------------------------------------------------------------------------
// FP16 flash attention, full-row warp ownership.
// NEW: 3-stage KV ring with CP_WAIT(1) — two loads in flight, latency slack.
// ---------------------------------------------------------------------------
#define FQLD 72
#define FVLD2 136
#define KV_STAGE_H (64 * FQLD + 64 * FVLD2)     // 13312 halfs
#define FSMEM_BYTES ((128 * FQLD + 3 * KV_STAGE_H) * 2)  // 98304 B

__device__ __forceinline__ void f_load_kv(__half* kbuf, const __half* __restrict__ Km,
                                          const __half* __restrict__ Vm,
                                          int brow0, int qoff, int voff, int tid) {
    __half* vbuf = kbuf + 64 * FQLD;
#pragma unroll
    for (int it = 0; it < 2; it++) {
        const int idx = tid + 256 * it;
        const int r = idx >> 3, sg = idx & 7;
        cpa16(smem_u32(kbuf + r * FQLD + sg * 8),
              Km + (size_t)(brow0 + r) * Ec + qoff + sg * 8);
    }
#pragma unroll
    for (int it = 0; it < 4; it++) {
        const int idx = tid + 256 * it;
        const int r = idx >> 4, sg = idx & 15;
        cpa16(smem_u32(vbuf + r * FVLD2 + sg * 8),
              Vm + (size_t)(brow0 + r) * Ec + voff + sg * 8);
    }
    CP_COMMIT();
}

__global__ __launch_bounds__(256) void flash_f16(
    const __half* __restrict__ Q, const __half* __restrict__ Km,
    const __half* __restrict__ Vm, float* __restrict__ O)
{
    extern __shared__ __align__(16) __half smh[];
    __half* Qs = smh;                       // 128*72
    __half* KV0 = Qs + 128 * FQLD;          // 3-stage ring: (K,V) per stage

    const int qtile = gridDim.x - 1 - blockIdx.x;   // longest CTAs first
    const int h2 = blockIdx.y;
    const int b = blockIdx.z;
    const int tid = threadIdx.x;
    const int wid = tid >> 5;
    const int lane = tid & 31;
    const int g = lane >> 2;
    const int tig = lane & 3;
    const int qm0 = qtile * 128;
    const int qoff = h2 * 64;
    const int voff = (h2 >> 1) * 128;
    const int ntiles = 2 * (qtile + 1);             // >= 2 always

    const int a_lrow = lane & 15;
    const int a_lcol = (lane >> 4) * 8;
    const int b_lrow = (lane & 7) + ((lane >> 4) << 3);
    const int b_lcol = ((lane >> 3) & 1) * 8;
    const int v_lrow = (lane & 7) + ((lane >> 3) & 1) * 8;
    const int v_lcol = ((lane >> 4) & 1) * 8;

    // ---- load Q tile ----
#pragma unroll
    for (int it = 0; it < 4; it++) {
        const int idx = tid + 256 * it;
        const int r = idx >> 3, sg = idx & 7;
        *(uint4*)(Qs + r * FQLD + sg * 8) =
            *(const uint4*)(Q + (size_t)(b * Tc + qm0 + r) * Ec + qoff + sg * 8);
    }
    __syncthreads();

    // ---- Q fragments (held all block) ----
    uint32_t qfr[4][4];
    {
        const uint32_t qb = smem_u32(Qs) +
            (uint32_t)(((wid * 16 + a_lrow) * FQLD + a_lcol) * 2);
#pragma unroll
        for (int kd = 0; kd < 4; kd++)
            LDSM_X4(qfr[kd], qb + (uint32_t)(kd * 32));
    }

    float oacc[16][4];
#pragma unroll
    for (int j = 0; j < 16; j++)
#pragma unroll
        for (int r = 0; r < 4; r++) oacc[j][r] = 0.f;
    float mrow0 = -1e30f, mrow1 = -1e30f;
    float lrow0 = 0.f, lrow1 = 0.f;
    const int rowa = qm0 + wid * 16 + g;

    // prologue: stages 0,1 <- tiles 0,1 (ntiles >= 2)
    f_load_kv(KV0, Km, Vm, b * Tc, qoff, voff, tid);
    f_load_kv(KV0 + KV_STAGE_H, Km, Vm, b * Tc + 64, qoff, voff, tid);

    for (int kt = 0; kt < ntiles; kt++) {
        if (kt + 2 < ntiles) CP_WAIT(1); else CP_WAIT(0);
        __syncthreads();
        // one barrier: publishes stage kt, proves stage (kt+2)%3's readers
        // (iteration kt-1) are done -> safe to refill.
        if (kt + 2 < ntiles)
            f_load_kv(KV0 + ((kt + 2) % 3) * KV_STAGE_H, Km, Vm,
                      b * Tc + (kt + 2) * 64, qoff, voff, tid);

        const __half* Kbuf = KV0 + (kt % 3) * KV_STAGE_H;
        const __half* Vbuf = Kbuf + 64 * FQLD;
        const uint32_t ksb = smem_u32(Kbuf) + (uint32_t)((b_lrow * FQLD + b_lcol) * 2);
        const uint32_t vsb = smem_u32(Vbuf) + (uint32_t)((v_lrow * FVLD2 + v_lcol) * 2);

        // ---- S = Q @ K^T ----
        float sacc[8][4];
#pragma unroll
        for (int j = 0; j < 8; j++)
#pragma unroll
            for (int r = 0; r < 4; r++) sacc[j][r] = 0.f;
#pragma unroll
        for (int kd = 0; kd < 4; kd++) {
#pragma unroll
            for (int jp = 0; jp < 4; jp++) {
                uint32_t bl[4];
                LDSM_X4(bl, ksb + (uint32_t)((jp * 16 * FQLD + kd * 16) * 2));
                mma_f16(sacc[2 * jp], qfr[kd], bl);
                mma_f16(sacc[2 * jp + 1], qfr[kd], bl + 2);
            }
        }

        // ---- causal mask ----
        if (kt * 64 + 63 > rowa) {
#pragma unroll
            for (int j = 0; j < 8; j++) {
                const int colb = kt * 64 + j * 8 + 2 * tig;
                if (colb > rowa) sacc[j][0] = -1e30f;
                if (colb + 1 > rowa) sacc[j][1] = -1e30f;
                if (colb > rowa + 8) sacc[j][2] = -1e30f;
                if (colb + 1 > rowa + 8) sacc[j][3] = -1e30f;
            }
        }

        // ---- warp-local online softmax ----
        float m0 = -1e30f, m1 = -1e30f;
#pragma unroll
        for (int j = 0; j < 8; j++) {
            m0 = fmaxf(m0, fmaxf(sacc[j][0], sacc[j][1]));
            m1 = fmaxf(m1, fmaxf(sacc[j][2], sacc[j][3]));
        }
#pragma unroll
        for (int off = 1; off <= 2; off <<= 1) {
            m0 = fmaxf(m0, __shfl_xor_sync(0xffffffffu, m0, off));
            m1 = fmaxf(m1, __shfl_xor_sync(0xffffffffu, m1, off));
        }
        const float mn0 = fmaxf(mrow0, m0);
        const float mn1 = fmaxf(mrow1, m1);
        const float al0 = __expf(mrow0 - mn0);
        const float al1 = __expf(mrow1 - mn1);
        mrow0 = mn0; mrow1 = mn1;

        float s0 = 0.f, s1 = 0.f;
#pragma unroll
        for (int j = 0; j < 8; j++) {
            sacc[j][0] = __expf(sacc[j][0] - mn0);
            sacc[j][1] = __expf(sacc[j][1] - mn0);
            sacc[j][2] = __expf(sacc[j][2] - mn1);
            sacc[j][3] = __expf(sacc[j][3] - mn1);
            s0 += sacc[j][0] + sacc[j][1];
            s1 += sacc[j][2] + sacc[j][3];
        }
#pragma unroll
        for (int off = 1; off <= 2; off <<= 1) {
            s0 += __shfl_xor_sync(0xffffffffu, s0, off);
            s1 += __shfl_xor_sync(0xffffffffu, s1, off);
        }
        lrow0 = lrow0 * al0 + s0;
        lrow1 = lrow1 * al1 + s1;
#pragma unroll
        for (int j = 0; j < 16; j++) {
            oacc[j][0] *= al0; oacc[j][1] *= al0;
            oacc[j][2] *= al1; oacc[j][3] *= al1;
        }

        // ---- O += P @ V ----
#pragma unroll
        for (int kn = 0; kn < 4; kn++) {
            uint32_t aP[4];
            aP[0] = pack_h2(sacc[2 * kn][0], sacc[2 * kn][1]);
            aP[1] = pack_h2(sacc[2 * kn][2], sacc[2 * kn][3]);
            aP[2] = pack_h2(sacc[2 * kn + 1][0], sacc[2 * kn + 1][1]);
            aP[3] = pack_h2(sacc[2 * kn + 1][2], sacc[2 * kn + 1][3]);
#pragma unroll
            for (int jp = 0; jp < 8; jp++) {
                uint32_t vl[4];
                LDSM_X4_T(vl, vsb + (uint32_t)((kn * 16 * FVLD2 + jp * 16) * 2));
                mma_f16(oacc[2 * jp], aP, vl);
                mma_f16(oacc[2 * jp + 1], aP, vl + 2);
            }
        }
    }

    // ---- epilogue ----
    const float inv0 = 1.f / lrow0;
    const float inv1 = 1.f / lrow1;
    float* obase = O + ((size_t)(b * 2 * Hc + h2) * Tc + rowa) * 128;
#pragma unroll
    for (int j = 0; j < 16; j++) {
        const int col = j * 8 + 2 * tig;
        *(float2*)(obase + col) = make_float2(oacc[j][0] * inv0, oacc[j][1] * inv0);
        *(float2*)(obase + 8 * 128 + col) = make_float2(oacc[j][2] * inv1, oacc[j][3] * inv1);
    }
}

// ---------------------------------------------------------------------------
// Combine: warp per row. x = O[2h] - lam*O[2h+1]; RMSNorm(128); * g * (1-LI)
// ---------------------------------------------------------------------------
__global__ __launch_bounds__(256) void combine_kernel(
    const float* __restrict__ O, const float* __restrict__ gw,
    __half* __restrict__ ctx)
{
    const int lane = threadIdx.x & 31;
    const int idx = blockIdx.x * 8 + (threadIdx.x >> 5);
    const int t = idx % Tc;
    const int h = (idx / Tc) % Hc;
    const int b = idx / (Tc * Hc);

    const size_t base1 = ((size_t)(b * 2 * Hc + 2 * h) * Tc + t) * 128 + lane * 4;
    const size_t base2 = base1 + (size_t)Tc * 128;

    const float lam = g_lam;
    float4 o1 = *(const float4*)(O + base1);
    float4 o2 = *(const float4*)(O + base2);
    float4 x;
    x.x = o1.x - lam * o2.x;
    x.y = o1.y - lam * o2.y;
    x.z = o1.z - lam * o2.z;
    x.w = o1.w - lam * o2.w;

    float v = x.x * x.x + x.y * x.y + x.z * x.z + x.w * x.w;
#pragma unroll
    for (int off = 16; off > 0; off >>= 1)
        v += __shfl_xor_sync(0xffffffffu, v, off);

    const float rms = rsqrtf(v * (1.f / 128.f) + 1e-5f);
    const float LI = 0.8f - 0.6f * expf(-3.6f);
    const float s = rms * (1.f - LI);
    float4 gv = *(const float4*)(gw + lane * 4);

    __half2 h01 = __floats2half2_rn(x.x * s * gv.x, x.y * s * gv.y);
    __half2 h23 = __floats2half2_rn(x.z * s * gv.z, x.w * s * gv.w);
    __half2* dst = (__half2*)(ctx + (size_t)(b * Tc + t) * Ec + h * 128 + lane * 4);
    dst[0] = h01;
    dst[1] = h23;
}

// ---------------------------------------------------------------------------
// Host launcher
// ---------------------------------------------------------------------------
extern "C" void kernel_launch(void* const* d_in, const int* in_sizes, int n_in,
                              void* d_out, int out_size)
{
    (void)in_sizes; (void)n_in; (void)out_size;

    const float* query = (const float*)d_in[0];
    const float* Wq = (const float*)d_in[1];
    const float* Wk = (const float*)d_in[2];
    const float* Wv = (const float*)d_in[3];
    const float* Wo = (const float*)d_in[4];
    const float* lq1 = (const float*)d_in[5];
    const float* lk1 = (const float*)d_in[6];
    const float* lq2 = (const float*)d_in[7];
    const float* lk2 = (const float*)d_in[8];
    const float* gw = (const float*)d_in[9];
    float* out = (float*)d_out;

    __half *pQ, *pK, *pV, *pC, *pXh, *pWh;
    float *pO;
    cudaGetSymbolAddress((void**)&pQ, g_Q);
    cudaGetSymbolAddress((void**)&pK, g_K);
    cudaGetSymbolAddress((void**)&pV, g_V);
    cudaGetSymbolAddress((void**)&pO, g_O);
    cudaGetSymbolAddress((void**)&pC, g_ctx);
    cudaGetSymbolAddress((void**)&pXh, g_Xh);
    cudaGetSymbolAddress((void**)&pWh, g_Wh);

    cudaFuncSetAttribute(gemm_qkv, cudaFuncAttributeMaxDynamicSharedMemorySize, GSMEM_BYTES);
    cudaFuncSetAttribute(gemm_wo, cudaFuncAttributeMaxDynamicSharedMemorySize, GSMEM_BYTES);
    cudaFuncSetAttribute(flash_f16, cudaFuncAttributeMaxDynamicSharedMemorySize, FSMEM_BYTES);

    const int NW4 = (Ec * Ec) / 4;
    const int NX4 = (MTOT * Ec) / 4;
    const int RB = 256;

    // conversions up front
    cvt_f2h_kernel<<<(NX4 + RB - 1) / RB, RB>>>(query, pXh, NX4);
    cvt_w4_kernel<<<dim3(NW4 / RB, 4), RB>>>(Wq, Wk, Wv, Wo, pWh);
    lambda_kernel<<<1, 1>>>(lq1, lk1, lq2, lk2);

    // fused Q/K/V projections
    gemm_qkv<<<dim3(Ec / BN, MTOT / BM, 3), GTHREADS, GSMEM_BYTES>>>(pXh, pWh, pQ, pK, pV);

    // flash attention (3-stage KV pipeline)
    flash_f16<<<dim3(Tc / 128, 2 * Hc, Bc), 256, FSMEM_BYTES>>>(pQ, pK, pV, pO);

    combine_kernel<<<Bc * Hc * Tc / 8, 256>>>(pO, gw, pC);

    // output projection (fp32 out) — R12-proven 128x128 tiles
    gemm_wo<<<dim3(Ec / BN, MTOT / BM), GTHREADS, GSMEM_BYTES>>>(pC, pWh + 3 * (size_t)Ec * Ec, out);
}

// round 16
// speedup vs baseline: 1.0522x; 1.0522x over previous
#include <cuda_runtime.h>
#include <cuda_fp16.h>
#include <cstdint>
#include <math.h>

// Problem constants
#define Bc 2
#define Tc 2048
#define Ec 2048
#define Hc 16
#define Dc 64
#define MTOT (Bc * Tc)  // 4096

// ---------------------------------------------------------------------------
// Device scratch (no allocations allowed)
// ---------------------------------------------------------------------------
__device__ __half g_Q[Bc * Tc * Ec];                      // fp16, pre-scaled
__device__ __half g_K[Bc * Tc * Ec];                      // fp16
__device__ __half g_V[Bc * Tc * Ec];                      // fp16
__device__ float  g_O[(size_t)Bc * 2 * Hc * Tc * 2 * Dc]; // [B, 2H, T, 128] fp32
__device__ __half g_ctx[Bc * Tc * Ec];                    // fp16
__device__ __half g_Xh[MTOT * Ec];                        // fp16 query
__device__ __half g_Wh[4 * Ec * Ec];                      // fp16 weights (q,k,v,o)
__device__ float  g_lam;

// ---------------------------------------------------------------------------
// PTX helpers
// ---------------------------------------------------------------------------
__device__ __forceinline__ uint32_t smem_u32(const void* p) {
    uint32_t a;
    asm("{ .reg .u64 t; cvta.to.shared.u64 t, %1; cvt.u32.u64 %0, t; }" : "=r"(a) : "l"(p));
    return a;
}
__device__ __forceinline__ void cpa16(uint32_t saddr, const void* g) {
    asm volatile("cp.async.cg.shared.global [%0], [%1], 16;" :: "r"(saddr), "l"(g));
}
#define CP_COMMIT() asm volatile("cp.async.commit_group;" ::: "memory")
#define CP_WAIT(n) asm volatile("cp.async.wait_group %0;" :: "n"(n) : "memory")

__device__ __forceinline__ void mma_f16(float* d, const uint32_t* a, const uint32_t* b) {
    asm volatile(
        "mma.sync.aligned.m16n8k16.row.col.f32.f16.f16.f32 "
        "{%0,%1,%2,%3}, {%4,%5,%6,%7}, {%8,%9}, {%0,%1,%2,%3};"
        : "+f"(d[0]), "+f"(d[1]), "+f"(d[2]), "+f"(d[3])
        : "r"(a[0]), "r"(a[1]), "r"(a[2]), "r"(a[3]), "r"(b[0]), "r"(b[1]));
}
#define LDSM_X4(r, addr) \
    asm volatile("ldmatrix.sync.aligned.m8n8.x4.shared.b16 {%0,%1,%2,%3}, [%4];" \
                 : "=r"((r)[0]), "=r"((r)[1]), "=r"((r)[2]), "=r"((r)[3]) : "r"(addr))
#define LDSM_X4_T(r, addr) \
    asm volatile("ldmatrix.sync.aligned.m8n8.x4.trans.shared.b16 {%0,%1,%2,%3}, [%4];" \
                 : "=r"((r)[0]), "=r"((r)[1]), "=r"((r)[2]), "=r"((r)[3]) : "r"(addr))

__device__ __forceinline__ uint32_t pack_h2(float lo, float hi) {
    __half2 h = __floats2half2_rn(lo, hi);
    return *(uint32_t*)&h;
}

// ---------------------------------------------------------------------------
// fp32 -> fp16 convert (1:1)
// ---------------------------------------------------------------------------
__global__ __launch_bounds__(256) void cvt_f2h_kernel(
    const float* __restrict__ in, __half* __restrict__ out, int n4)
{
    const int i = blockIdx.x * 256 + threadIdx.x;
    if (i < n4) {
        float4 v = *(const float4*)(in + 4 * (size_t)i);
        __half2* o = (__half2*)(out + 4 * (size_t)i);
        o[0] = __floats2half2_rn(v.x, v.y);
        o[1] = __floats2half2_rn(v.z, v.w);
    }
}

// All four weights in one launch (grid.y selects weight)
__global__ __launch_bounds__(256) void cvt_w4_kernel(
    const float* __restrict__ w0, const float* __restrict__ w1,
    const float* __restrict__ w2, const float* __restrict__ w3,
    __half* __restrict__ out)
{
    const int y = blockIdx.y;
    const float* src = (y == 0) ? w0 : (y == 1) ? w1 : (y == 2) ? w2 : w3;
    const int i = blockIdx.x * 256 + threadIdx.x;
    float4 v = *(const float4*)(src + 4 * (size_t)i);
    __half2* o = (__half2*)(out + (size_t)y * Ec * Ec + 4 * (size_t)i);
    o[0] = __floats2half2_rn(v.x, v.y);
    o[1] = __floats2half2_rn(v.z, v.w);
}

// ---------------------------------------------------------------------------
// GEMM: CTA 128x128, 4 warps (2x2), warp tile 64x64, BK=64.
// 3-stage cp.async ring (CP_WAIT(1): one 36KB stage always in flight),
// one barrier per K-tile (32 total, halved vs BK=32), natural registers.
// Same k16-chunk accumulation order as R12 -> bit-identical output.
// ---------------------------------------------------------------------------
#define BM 128
#define BN 128
#define BK 64
#define HLDA 72
#define STAGE_H (BM * HLDA)                      // 9216 halfs per matrix
#define GSMEM_BYTES (3 * 2 * STAGE_H * 2)        // 110592 B
#define GTHREADS 128

__device__ __forceinline__ void g_stage_load(__half* stage, const __half* __restrict__ X,
                                             const __half* __restrict__ W,
                                             int m0, int n0, int K, int kt, int tid) {
    __half* Ad = stage;
    __half* Bd = stage + STAGE_H;
    const int kcol = kt * BK;
#pragma unroll
    for (int i = 0; i < 8; i++) {
        const int c = tid + GTHREADS * i;     // 0..1023
        const int r = c >> 3, sg = c & 7;     // row 0..127, 16B seg 0..7
        cpa16(smem_u32(Ad + r * HLDA + sg * 8), X + (size_t)(m0 + r) * K + kcol + sg * 8);
        cpa16(smem_u32(Bd + r * HLDA + sg * 8), W + (size_t)(n0 + r) * K + kcol + sg * 8);
    }
    CP_COMMIT();
}

__device__ __forceinline__ void gemm_core(
    const __half* __restrict__ X, const __half* __restrict__ W,
    float* __restrict__ Cf, __half* __restrict__ Ch,
    int m0, int n0, float alpha, int out_half, __half* smem)
{
    const int N = Ec, K = Ec;
    const int tid = threadIdx.x;
    const int wid = tid >> 5;
    const int lane = tid & 31;
    const int g = lane >> 2;
    const int tig = lane & 3;
    const int warp_m = (wid & 1) * 64;
    const int warp_n = (wid >> 1) * 64;
    const int NK = K / BK;                    // 32

    const uint32_t sb = smem_u32(smem);
    const uint32_t a_off = (uint32_t)(((warp_m + (lane & 15)) * HLDA + (lane >> 4) * 8) * 2);
    const uint32_t b_off = (uint32_t)((STAGE_H + (warp_n + (lane & 7) + ((lane >> 4) << 3)) * HLDA
                                      + ((lane >> 3) & 1) * 8) * 2);

    float acc[4][8][4];
#pragma unroll
    for (int i = 0; i < 4; i++)
#pragma unroll
        for (int j = 0; j < 8; j++)
#pragma unroll
            for (int r = 0; r < 4; r++) acc[i][j][r] = 0.f;

    g_stage_load(smem, X, W, m0, n0, K, 0, tid);
    g_stage_load(smem + 2 * STAGE_H, X, W, m0, n0, K, 1, tid);

    for (int kt = 0; kt < NK; kt++) {
        const int p = kt % 3;
        if (kt + 2 < NK) CP_WAIT(1); else CP_WAIT(0);
        __syncthreads();
        if (kt + 2 < NK)
            g_stage_load(smem + ((kt + 2) % 3) * 2 * STAGE_H, X, W, m0, n0, K, kt + 2, tid);

        const uint32_t stg = sb + (uint32_t)(p * 2 * STAGE_H * 2);
#pragma unroll
        for (int kc = 0; kc < 4; kc++) {              // four k16 chunks in BK=64
            const uint32_t ko = (uint32_t)(kc * 32);  // 16 halfs = 32B
            uint32_t afr[4][4], bfr[4][4];
#pragma unroll
            for (int i = 0; i < 4; i++)
                LDSM_X4(afr[i], stg + a_off + (uint32_t)(i * 16 * HLDA * 2) + ko);
#pragma unroll
            for (int j2 = 0; j2 < 4; j2++)
                LDSM_X4(bfr[j2], stg + b_off + (uint32_t)(j2 * 16 * HLDA * 2) + ko);
#pragma unroll
            for (int i = 0; i < 4; i++)
#pragma unroll
                for (int j = 0; j < 8; j++)
                    mma_f16(acc[i][j], afr[i], bfr[j >> 1] + (j & 1) * 2);
        }
    }

#pragma unroll
    for (int i = 0; i < 4; i++) {
#pragma unroll
        for (int j = 0; j < 8; j++) {
            const int row = m0 + warp_m + i * 16 + g;
            const int col = n0 + warp_n + j * 8 + 2 * tig;
            const float c0 = acc[i][j][0] * alpha, c1 = acc[i][j][1] * alpha;
            const float c2 = acc[i][j][2] * alpha, c3 = acc[i][j][3] * alpha;
            if (out_half) {
                *(__half2*)(Ch + (size_t)row * N + col) = __floats2half2_rn(c0, c1);
                *(__half2*)(Ch + (size_t)(row + 8) * N + col) = __floats2half2_rn(c2, c3);
            } else {
                *(float2*)(Cf + (size_t)row * N + col) = make_float2(c0, c1);
                *(float2*)(Cf + (size_t)(row + 8) * N + col) = make_float2(c2, c3);
            }
        }
    }
}

// Fused Q/K/V projections: grid.z selects weight/output/alpha.
__global__ __launch_bounds__(GTHREADS) void gemm_qkv(
    const __half* __restrict__ X, const __half* __restrict__ Wb,
    __half* __restrict__ Qo, __half* __restrict__ Ko, __half* __restrict__ Vo)
{
    extern __shared__ __align__(16) __half smem[];
    const int z = blockIdx.z;
    const __half* W = Wb + (size_t)z * Ec * Ec;
    __half* Ch = (z == 0) ? Qo : (z == 1) ? Ko : Vo;
    const float alpha = (z == 0) ? 0.125f : 1.0f;
    gemm_core(X, W, nullptr, Ch, blockIdx.y * BM, blockIdx.x * BN, alpha, 1, smem);
}

// Output projection (fp32 out)
__global__ __launch_bounds__(GTHREADS) void gemm_wo(
    const __half* __restrict__ X, const __half* __restrict__ W,
    float* __restrict__ Cf)
{
    extern __shared__ __align__(16) __half smem[];
    gemm_core(X, W, Cf, nullptr, blockIdx.y * BM, blockIdx.x * BN, 1.0f, 0, smem);
}

// ---------------------------------------------------------------------------
// Lambda scalar
// ---------------------------------------------------------------------------
__global__ void lambda_kernel(const float* __restrict__ lq1, const float* __restrict__ lk1,
                              const float* __restrict__ lq2, const float* __restrict__ lk2)
{
    float s1 = 0.f, s2 = 0.f;
    for (int i = 0; i < Dc; i++) {
        s1 += lq1[i] * lk1[i];
        s2 += lq2[i] * lk2[i];
    }
    const float LI = 0.8f - 0.6f * expf(-3.6f);
    g_lam = expf(s1) - expf(s2) + LI;
}

// ---------------------------------------------------------------------------
// FP16 flash attention, full-row warp ownership. (exact R12 form: 2-stage KV)
// ---------------------------------------------------------------------------
#define FQLD 72
#define FVLD2 136
#define KV_STAGE_H (64 * FQLD + 64 * FVLD2)     // 13312 halfs
#define FSMEM_BYTES ((128 * FQLD + 2 * KV_STAGE_H) * 2)  // 71680 B

__device__ __forceinline__ void f_load_kv(__half* kbuf, const __half* __restrict__ Km,
                                          const __half* __restrict__ Vm,
                                          int brow0, int qoff, int voff, int tid) {
    __half* vbuf = kbuf + 64 * FQLD;
#pragma unroll
    for (int it = 0; it < 2; it++) {
        const int idx = tid + 256 * it;
        const int r = idx >> 3, sg = idx & 7;
        cpa16(smem_u32(kbuf + r * FQLD + sg * 8),
              Km + (size_t)(brow0 + r) * Ec + qoff + sg * 8);
    }
#pragma unroll
    for (int it = 0; it < 4; it++) {
        const int idx = tid + 256 * it;
        const int r = idx >> 4, sg = idx & 15;
        cpa16(smem_u32(vbuf + r * FVLD2 + sg * 8),
              Vm + (size_t)(brow0 + r) * Ec + voff + sg * 8);
    }
    CP_COMMIT();
}

__global__ __launch_bounds__(256) void flash_f16(
    const __half* __restrict__ Q, const __half* __restrict__ Km,
    const __half* __restrict__ Vm, float* __restrict__ O)
{
    extern __shared__ __align__(16) __half smh[];
    __half* Qs = smh;                       // 128*72
    __half* KV0 = Qs + 128 * FQLD;          // 2-stage: (K,V) per stage

    const int qtile = gridDim.x - 1 - blockIdx.x;   // longest CTAs first
    const int h2 = blockIdx.y;
    const int b = blockIdx.z;
    const int tid = threadIdx.x;
    const int wid = tid >> 5;
    const int lane = tid & 31;
    const int g = lane >> 2;
    const int tig = lane & 3;
    const int qm0 = qtile * 128;
    const int qoff = h2 * 64;
    const int voff = (h2 >> 1) * 128;
    const int ntiles = 2 * (qtile + 1);

    const int a_lrow = lane & 15;
    const int a_lcol = (lane >> 4) * 8;
    const int b_lrow = (lane & 7) + ((lane >> 4) << 3);
    const int b_lcol = ((lane >> 3) & 1) * 8;
    const int v_lrow = (lane & 7) + ((lane >> 3) & 1) * 8;
    const int v_lcol = ((lane >> 4) & 1) * 8;

    // ---- load Q tile ----
#pragma unroll
    for (int it = 0; it < 4; it++) {
        const int idx = tid + 256 * it;
        const int r = idx >> 3, sg = idx & 7;
        *(uint4*)(Qs + r * FQLD + sg * 8) =
            *(const uint4*)(Q + (size_t)(b * Tc + qm0 + r) * Ec + qoff + sg * 8);
    }
    __syncthreads();

    // ---- Q fragments (held all block) ----
    uint32_t qfr[4][4];
    {
        const uint32_t qb = smem_u32(Qs) +
            (uint32_t)(((wid * 16 + a_lrow) * FQLD + a_lcol) * 2);
#pragma unroll
        for (int kd = 0; kd < 4; kd++)
            LDSM_X4(qfr[kd], qb + (uint32_t)(kd * 32));
    }

    float oacc[16][4];
#pragma unroll
    for (int j = 0; j < 16; j++)
#pragma unroll
        for (int r = 0; r < 4; r++) oacc[j][r] = 0.f;
    float mrow0 = -1e30f, mrow1 = -1e30f;
    float lrow0 = 0.f, lrow1 = 0.f;
    const int rowa = qm0 + wid * 16 + g;

    f_load_kv(KV0, Km, Vm, b * Tc, qoff, voff, tid);

    for (int kt = 0; kt < ntiles; kt++) {
        CP_WAIT(0);
        __syncthreads();
        if (kt + 1 < ntiles)
            f_load_kv(KV0 + ((kt + 1) & 1) * KV_STAGE_H, Km, Vm,
                      b * Tc + (kt + 1) * 64, qoff, voff, tid);

        const __half* Kbuf = KV0 + (kt & 1) * KV_STAGE_H;
        const __half* Vbuf = Kbuf + 64 * FQLD;
        const uint32_t ksb = smem_u32(Kbuf) + (uint32_t)((b_lrow * FQLD + b_lcol) * 2);
        const uint32_t vsb = smem_u32(Vbuf) + (uint32_t)((v_lrow * FVLD2 + v_lcol) * 2);

        // ---- S = Q @ K^T ----
        float sacc[8][4];
#pragma unroll
        for (int j = 0; j < 8; j++)
#pragma unroll
            for (int r = 0; r < 4; r++) sacc[j][r] = 0.f;
#pragma unroll
        for (int kd = 0; kd < 4; kd++) {
#pragma unroll
            for (int jp = 0; jp < 4; jp++) {
                uint32_t bl[4];
                LDSM_X4(bl, ksb + (uint32_t)((jp * 16 * FQLD + kd * 16) * 2));
                mma_f16(sacc[2 * jp], qfr[kd], bl);
                mma_f16(sacc[2 * jp + 1], qfr[kd], bl + 2);
            }
        }

        // ---- causal mask ----
        if (kt * 64 + 63 > rowa) {
#pragma unroll
            for (int j = 0; j < 8; j++) {
                const int colb = kt * 64 + j * 8 + 2 * tig;
                if (colb > rowa) sacc[j][0] = -1e30f;
                if (colb + 1 > rowa) sacc[j][1] = -1e30f;
                if (colb > rowa + 8) sacc[j][2] = -1e30f;
                if (colb + 1 > rowa + 8) sacc[j][3] = -1e30f;
            }
        }

        // ---- warp-local online softmax ----
        float m0 = -1e30f, m1 = -1e30f;
#pragma unroll
        for (int j = 0; j < 8; j++) {
            m0 = fmaxf(m0, fmaxf(sacc[j][0], sacc[j][1]));
            m1 = fmaxf(m1, fmaxf(sacc[j][2], sacc[j][3]));
        }
#pragma unroll
        for (int off = 1; off <= 2; off <<= 1) {
            m0 = fmaxf(m0, __shfl_xor_sync(0xffffffffu, m0, off));
            m1 = fmaxf(m1, __shfl_xor_sync(0xffffffffu, m1, off));
        }
        const float mn0 = fmaxf(mrow0, m0);
        const float mn1 = fmaxf(mrow1, m1);
        const float al0 = __expf(mrow0 - mn0);
        const float al1 = __expf(mrow1 - mn1);
        mrow0 = mn0; mrow1 = mn1;

        float s0 = 0.f, s1 = 0.f;
#pragma unroll
        for (int j = 0; j < 8; j++) {
            sacc[j][0] = __expf(sacc[j][0] - mn0);
            sacc[j][1] = __expf(sacc[j][1] - mn0);
            sacc[j][2] = __expf(sacc[j][2] - mn1);
            sacc[j][3] = __expf(sacc[j][3] - mn1);
            s0 += sacc[j][0] + sacc[j][1];
            s1 += sacc[j][2] + sacc[j][3];
        }
#pragma unroll
        for (int off = 1; off <= 2; off <<= 1) {
            s0 += __shfl_xor_sync(0xffffffffu, s0, off);
            s1 += __shfl_xor_sync(0xffffffffu, s1, off);
        }
        lrow0 = lrow0 * al0 + s0;
        lrow1 = lrow1 * al1 + s1;
#pragma unroll
        for (int j = 0; j < 16; j++) {
            oacc[j][0] *= al0; oacc[j][1] *= al0;
            oacc[j][2] *= al1; oacc[j][3] *= al1;
        }

        // ---- O += P @ V ----
#pragma unroll
        for (int kn = 0; kn < 4; kn++) {
            uint32_t aP[4];
            aP[0] = pack_h2(sacc[2 * kn][0], sacc[2 * kn][1]);
            aP[1] = pack_h2(sacc[2 * kn][2], sacc[2 * kn][3]);
            aP[2] = pack_h2(sacc[2 * kn + 1][0], sacc[2 * kn + 1][1]);
            aP[3] = pack_h2(sacc[2 * kn + 1][2], sacc[2 * kn + 1][3]);
#pragma unroll
            for (int jp = 0; jp < 8; jp++) {
                uint32_t vl[4];
                LDSM_X4_T(vl, vsb + (uint32_t)((kn * 16 * FVLD2 + jp * 16) * 2));
                mma_f16(oacc[2 * jp], aP, vl);
                mma_f16(oacc[2 * jp + 1], aP, vl + 2);
            }
        }
    }

    // ---- epilogue ----
    const float inv0 = 1.f / lrow0;
    const float inv1 = 1.f / lrow1;
    float* obase = O + ((size_t)(b * 2 * Hc + h2) * Tc + rowa) * 128;
#pragma unroll
    for (int j = 0; j < 16; j++) {
        const int col = j * 8 + 2 * tig;
        *(float2*)(obase + col) = make_float2(oacc[j][0] * inv0, oacc[j][1] * inv0);
        *(float2*)(obase + 8 * 128 + col) = make_float2(oacc[j][2] * inv1, oacc[j][3] * inv1);
    }
}

// ---------------------------------------------------------------------------
// Combine: warp per row. x = O[2h] - lam*O[2h+1]; RMSNorm(128); * g * (1-LI)
// ---------------------------------------------------------------------------
__global__ __launch_bounds__(256) void combine_kernel(
    const float* __restrict__ O, const float* __restrict__ gw,
    __half* __restrict__ ctx)
{
    const int lane = threadIdx.x & 31;
    const int idx = blockIdx.x * 8 + (threadIdx.x >> 5);
    const int t = idx % Tc;
    const int h = (idx / Tc) % Hc;
    const int b = idx / (Tc * Hc);

    const size_t base1 = ((size_t)(b * 2 * Hc + 2 * h) * Tc + t) * 128 + lane * 4;
    const size_t base2 = base1 + (size_t)Tc * 128;

    const float lam = g_lam;
    float4 o1 = *(const float4*)(O + base1);
    float4 o2 = *(const float4*)(O + base2);
    float4 x;
    x.x = o1.x - lam * o2.x;
    x.y = o1.y - lam * o2.y;
    x.z = o1.z - lam * o2.z;
    x.w = o1.w - lam * o2.w;

    float v = x.x * x.x + x.y * x.y + x.z * x.z + x.w * x.w;
#pragma unroll
    for (int off = 16; off > 0; off >>= 1)
        v += __shfl_xor_sync(0xffffffffu, v, off);

    const float rms = rsqrtf(v * (1.f / 128.f) + 1e-5f);
    const float LI = 0.8f - 0.6f * expf(-3.6f);
    const float s = rms * (1.f - LI);
    float4 gv = *(const float4*)(gw + lane * 4);

    __half2 h01 = __floats2half2_rn(x.x * s * gv.x, x.y * s * gv.y);
    __half2 h23 = __floats2half2_rn(x.z * s * gv.z, x.w * s * gv.w);
    __half2* dst = (__half2*)(ctx + (size_t)(b * Tc + t) * Ec + h * 128 + lane * 4);
    dst[0] = h01;
    dst[1] = h23;
}

// ---------------------------------------------------------------------------
// Host launcher
// ---------------------------------------------------------------------------
extern "C" void kernel_launch(void* const* d_in, const int* in_sizes, int n_in,
                              void* d_out, int out_size)
{
    (void)in_sizes; (void)n_in; (void)out_size;

    const float* query = (const float*)d_in[0];
    const float* Wq = (const float*)d_in[1];
    const float* Wk = (const float*)d_in[2];
    const float* Wv = (const float*)d_in[3];
    const float* Wo = (const float*)d_in[4];
    const float* lq1 = (const float*)d_in[5];
    const float* lk1 = (const float*)d_in[6];
    const float* lq2 = (const float*)d_in[7];
    const float* lk2 = (const float*)d_in[8];
    const float* gw = (const float*)d_in[9];
    float* out = (float*)d_out;

    __half *pQ, *pK, *pV, *pC, *pXh, *pWh;
    float *pO;
    cudaGetSymbolAddress((void**)&pQ, g_Q);
    cudaGetSymbolAddress((void**)&pK, g_K);
    cudaGetSymbolAddress((void**)&pV, g_V);
    cudaGetSymbolAddress((void**)&pO, g_O);
    cudaGetSymbolAddress((void**)&pC, g_ctx);
    cudaGetSymbolAddress((void**)&pXh, g_Xh);
    cudaGetSymbolAddress((void**)&pWh, g_Wh);

    cudaFuncSetAttribute(gemm_qkv, cudaFuncAttributeMaxDynamicSharedMemorySize, GSMEM_BYTES);
    cudaFuncSetAttribute(gemm_wo, cudaFuncAttributeMaxDynamicSharedMemorySize, GSMEM_BYTES);
    cudaFuncSetAttribute(flash_f16, cudaFuncAttributeMaxDynamicSharedMemorySize, FSMEM_BYTES);

    const int NW4 = (Ec * Ec) / 4;
    const int NX4 = (MTOT * Ec) / 4;
    const int RB = 256;

    // conversions up front
    cvt_f2h_kernel<<<(NX4 + RB - 1) / RB, RB>>>(query, pXh, NX4);
    cvt_w4_kernel<<<dim3(NW4 / RB, 4), RB>>>(Wq, Wk, Wv, Wo, pWh);
    lambda_kernel<<<1, 1>>>(lq1, lk1, lq2, lk2);

    // fused Q/K/V projections (BK=64, 3-stage)
    gemm_qkv<<<dim3(Ec / BN, MTOT / BM, 3), GTHREADS, GSMEM_BYTES>>>(pXh, pWh, pQ, pK, pV);

    // flash attention (R12 2-stage KV)
    flash_f16<<<dim3(Tc / 128, 2 * Hc, Bc), 256, FSMEM_BYTES>>>(pQ, pK, pV, pO);

    combine_kernel<<<Bc * Hc * Tc / 8, 256>>>(pO, gw, pC);

    // output projection (fp32 out)
    gemm_wo<<<dim3(Ec / BN, MTOT / BM), GTHREADS, GSMEM_BYTES>>>(pC, pWh + 3 * (size_t)Ec * Ec, out);
}

// round 17
// speedup vs baseline: 1.0879x; 1.0339x over previous
#include <cuda_runtime.h>
#include <cuda_fp16.h>
#include <cstdint>
#include <math.h>

// Problem constants
#define Bc 2
#define Tc 2048
#define Ec 2048
#define Hc 16
#define Dc 64
#define MTOT (Bc * Tc)  // 4096

// ---------------------------------------------------------------------------
// Device scratch (no allocations allowed)
// ---------------------------------------------------------------------------
__device__ __half g_Q[Bc * Tc * Ec];                      // fp16, pre-scaled
__device__ __half g_K[Bc * Tc * Ec];                      // fp16
__device__ __half g_V[Bc * Tc * Ec];                      // fp16
__device__ __half g_ctx[Bc * Tc * Ec];                    // fp16
__device__ __half g_Xh[MTOT * Ec];                        // fp16 query
__device__ __half g_Wh[4 * Ec * Ec];                      // fp16 weights (q,k,v,o)
__device__ float  g_lam;

// ---------------------------------------------------------------------------
// PTX helpers
// ---------------------------------------------------------------------------
__device__ __forceinline__ uint32_t smem_u32(const void* p) {
    uint32_t a;
    asm("{ .reg .u64 t; cvta.to.shared.u64 t, %1; cvt.u32.u64 %0, t; }" : "=r"(a) : "l"(p));
    return a;
}
__device__ __forceinline__ void cpa16(uint32_t saddr, const void* g) {
    asm volatile("cp.async.cg.shared.global [%0], [%1], 16;" :: "r"(saddr), "l"(g));
}
#define CP_COMMIT() asm volatile("cp.async.commit_group;" ::: "memory")
#define CP_WAIT(n) asm volatile("cp.async.wait_group %0;" :: "n"(n) : "memory")

__device__ __forceinline__ void mma_f16(float* d, const uint32_t* a, const uint32_t* b) {
    asm volatile(
        "mma.sync.aligned.m16n8k16.row.col.f32.f16.f16.f32 "
        "{%0,%1,%2,%3}, {%4,%5,%6,%7}, {%8,%9}, {%0,%1,%2,%3};"
        : "+f"(d[0]), "+f"(d[1]), "+f"(d[2]), "+f"(d[3])
        : "r"(a[0]), "r"(a[1]), "r"(a[2]), "r"(a[3]), "r"(b[0]), "r"(b[1]));
}
#define LDSM_X4(r, addr) \
    asm volatile("ldmatrix.sync.aligned.m8n8.x4.shared.b16 {%0,%1,%2,%3}, [%4];" \
                 : "=r"((r)[0]), "=r"((r)[1]), "=r"((r)[2]), "=r"((r)[3]) : "r"(addr))
#define LDSM_X4_T(r, addr) \
    asm volatile("ldmatrix.sync.aligned.m8n8.x4.trans.shared.b16 {%0,%1,%2,%3}, [%4];" \
                 : "=r"((r)[0]), "=r"((r)[1]), "=r"((r)[2]), "=r"((r)[3]) : "r"(addr))

__device__ __forceinline__ uint32_t pack_h2(float lo, float hi) {
    __half2 h = __floats2half2_rn(lo, hi);
    return *(uint32_t*)&h;
}

// ---------------------------------------------------------------------------
// fp32 -> fp16 convert (1:1)
// ---------------------------------------------------------------------------
__global__ __launch_bounds__(256) void cvt_f2h_kernel(
    const float* __restrict__ in, __half* __restrict__ out, int n4)
{
    const int i = blockIdx.x * 256 + threadIdx.x;
    if (i < n4) {
        float4 v = *(const float4*)(in + 4 * (size_t)i);
        __half2* o = (__half2*)(out + 4 * (size_t)i);
        o[0] = __floats2half2_rn(v.x, v.y);
        o[1] = __floats2half2_rn(v.z, v.w);
    }
}

// All four weights in one launch (grid.y selects weight)
__global__ __launch_bounds__(256) void cvt_w4_kernel(
    const float* __restrict__ w0, const float* __restrict__ w1,
    const float* __restrict__ w2, const float* __restrict__ w3,
    __half* __restrict__ out)
{
    const int y = blockIdx.y;
    const float* src = (y == 0) ? w0 : (y == 1) ? w1 : (y == 2) ? w2 : w3;
    const int i = blockIdx.x * 256 + threadIdx.x;
    float4 v = *(const float4*)(src + 4 * (size_t)i);
    __half2* o = (__half2*)(out + (size_t)y * Ec * Ec + 4 * (size_t)i);
    o[0] = __floats2half2_rn(v.x, v.y);
    o[1] = __floats2half2_rn(v.z, v.w);
}

// ---------------------------------------------------------------------------
// GEMM (R16-proven): CTA 128x128, 4 warps (2x2), warp tile 64x64, BK=64.
// 3-stage cp.async ring (CP_WAIT(1)), one barrier per K-tile, natural regs.
// ---------------------------------------------------------------------------
#define BM 128
#define BN 128
#define BK 64
#define HLDA 72
#define STAGE_H (BM * HLDA)                      // 9216 halfs per matrix
#define GSMEM_BYTES (3 * 2 * STAGE_H * 2)        // 110592 B
#define GTHREADS 128

__device__ __forceinline__ void g_stage_load(__half* stage, const __half* __restrict__ X,
                                             const __half* __restrict__ W,
                                             int m0, int n0, int K, int kt, int tid) {
    __half* Ad = stage;
    __half* Bd = stage + STAGE_H;
    const int kcol = kt * BK;
#pragma unroll
    for (int i = 0; i < 8; i++) {
        const int c = tid + GTHREADS * i;     // 0..1023
        const int r = c >> 3, sg = c & 7;
        cpa16(smem_u32(Ad + r * HLDA + sg * 8), X + (size_t)(m0 + r) * K + kcol + sg * 8);
        cpa16(smem_u32(Bd + r * HLDA + sg * 8), W + (size_t)(n0 + r) * K + kcol + sg * 8);
    }
    CP_COMMIT();
}

__device__ __forceinline__ void gemm_core(
    const __half* __restrict__ X, const __half* __restrict__ W,
    float* __restrict__ Cf, __half* __restrict__ Ch,
    int m0, int n0, float alpha, int out_half, __half* smem)
{
    const int N = Ec, K = Ec;
    const int tid = threadIdx.x;
    const int wid = tid >> 5;
    const int lane = tid & 31;
    const int g = lane >> 2;
    const int tig = lane & 3;
    const int warp_m = (wid & 1) * 64;
    const int warp_n = (wid >> 1) * 64;
    const int NK = K / BK;

    const uint32_t sb = smem_u32(smem);
    const uint32_t a_off = (uint32_t)(((warp_m + (lane & 15)) * HLDA + (lane >> 4) * 8) * 2);
    const uint32_t b_off = (uint32_t)((STAGE_H + (warp_n + (lane & 7) + ((lane >> 4) << 3)) * HLDA
                                      + ((lane >> 3) & 1) * 8) * 2);

    float acc[4][8][4];
#pragma unroll
    for (int i = 0; i < 4; i++)
#pragma unroll
        for (int j = 0; j < 8; j++)
#pragma unroll
            for (int r = 0; r < 4; r++) acc[i][j][r] = 0.f;

    g_stage_load(smem, X, W, m0, n0, K, 0, tid);
    g_stage_load(smem + 2 * STAGE_H, X, W, m0, n0, K, 1, tid);

    for (int kt = 0; kt < NK; kt++) {
        const int p = kt % 3;
        if (kt + 2 < NK) CP_WAIT(1); else CP_WAIT(0);
        __syncthreads();
        if (kt + 2 < NK)
            g_stage_load(smem + ((kt + 2) % 3) * 2 * STAGE_H, X, W, m0, n0, K, kt + 2, tid);

        const uint32_t stg = sb + (uint32_t)(p * 2 * STAGE_H * 2);
#pragma unroll
        for (int kc = 0; kc < 4; kc++) {
            const uint32_t ko = (uint32_t)(kc * 32);
            uint32_t afr[4][4], bfr[4][4];
#pragma unroll
            for (int i = 0; i < 4; i++)
                LDSM_X4(afr[i], stg + a_off + (uint32_t)(i * 16 * HLDA * 2) + ko);
#pragma unroll
            for (int j2 = 0; j2 < 4; j2++)
                LDSM_X4(bfr[j2], stg + b_off + (uint32_t)(j2 * 16 * HLDA * 2) + ko);
#pragma unroll
            for (int i = 0; i < 4; i++)
#pragma unroll
                for (int j = 0; j < 8; j++)
                    mma_f16(acc[i][j], afr[i], bfr[j >> 1] + (j & 1) * 2);
        }
    }

#pragma unroll
    for (int i = 0; i < 4; i++) {
#pragma unroll
        for (int j = 0; j < 8; j++) {
            const int row = m0 + warp_m + i * 16 + g;
            const int col = n0 + warp_n + j * 8 + 2 * tig;
            const float c0 = acc[i][j][0] * alpha, c1 = acc[i][j][1] * alpha;
            const float c2 = acc[i][j][2] * alpha, c3 = acc[i][j][3] * alpha;
            if (out_half) {
                *(__half2*)(Ch + (size_t)row * N + col) = __floats2half2_rn(c0, c1);
                *(__half2*)(Ch + (size_t)(row + 8) * N + col) = __floats2half2_rn(c2, c3);
            } else {
                *(float2*)(Cf + (size_t)row * N + col) = make_float2(c0, c1);
                *(float2*)(Cf + (size_t)(row + 8) * N + col) = make_float2(c2, c3);
            }
        }
    }
}

// Fused Q/K/V projections: grid.z selects weight/output/alpha.
__global__ __launch_bounds__(GTHREADS) void gemm_qkv(
    const __half* __restrict__ X, const __half* __restrict__ Wb,
    __half* __restrict__ Qo, __half* __restrict__ Ko, __half* __restrict__ Vo)
{
    extern __shared__ __align__(16) __half smem[];
    const int z = blockIdx.z;
    const __half* W = Wb + (size_t)z * Ec * Ec;
    __half* Ch = (z == 0) ? Qo : (z == 1) ? Ko : Vo;
    const float alpha = (z == 0) ? 0.125f : 1.0f;
    gemm_core(X, W, nullptr, Ch, blockIdx.y * BM, blockIdx.x * BN, alpha, 1, smem);
}

// Output projection (fp32 out)
__global__ __launch_bounds__(GTHREADS) void gemm_wo(
    const __half* __restrict__ X, const __half* __restrict__ W,
    float* __restrict__ Cf)
{
    extern __shared__ __align__(16) __half smem[];
    gemm_core(X, W, Cf, nullptr, blockIdx.y * BM, blockIdx.x * BN, 1.0f, 0, smem);
}

// ---------------------------------------------------------------------------
// Lambda scalar
// ---------------------------------------------------------------------------
__global__ void lambda_kernel(const float* __restrict__ lq1, const float* __restrict__ lk1,
                              const float* __restrict__ lq2, const float* __restrict__ lk2)
{
    float s1 = 0.f, s2 = 0.f;
    for (int i = 0; i < Dc; i++) {
        s1 += lq1[i] * lk1[i];
        s2 += lq2[i] * lk2[i];
    }
    const float LI = 0.8f - 0.6f * expf(-3.6f);
    g_lam = expf(s1) - expf(s2) + LI;
}

// ---------------------------------------------------------------------------
// Fused flash attention + differential combine + RMSNorm -> fp16 ctx.
// Grid (T/64 [reversed], H=16, B), 256 threads (8 warps).
// Warps 0-3: head h2=2h; warps 4-7: head h2=2h+1. Same 64 Q rows.
// Q/K cols for the pair are contiguous (h*128..+127); V shared (h*128..+127).
// 2-stage KV (K 64x128 + V 64x128 per stage). Epilogue: half-1 stashes
// normalized O2 in freed KV smem; half-0 combines, RMSNorms, writes ctx.
// ---------------------------------------------------------------------------
#define F2LD 136
#define KV2_STAGE (2 * 64 * F2LD)                 // K+V halfs = 17408
#define FF_SMEM_BYTES ((64 * F2LD + 2 * KV2_STAGE) * 2)  // 87040 B
#define X2LD 132

__device__ __forceinline__ void ff_load_kv(__half* kbuf, const __half* __restrict__ Km,
                                           const __half* __restrict__ Vm,
                                           int brow0, int coff, int tid) {
    __half* vbuf = kbuf + 64 * F2LD;
#pragma unroll
    for (int it = 0; it < 4; it++) {
        const int idx = tid + 256 * it;        // 0..1023
        const int r = idx >> 4, sg = idx & 15;
        cpa16(smem_u32(kbuf + r * F2LD + sg * 8),
              Km + (size_t)(brow0 + r) * Ec + coff + sg * 8);
    }
#pragma unroll
    for (int it = 0; it < 4; it++) {
        const int idx = tid + 256 * it;
        const int r = idx >> 4, sg = idx & 15;
        cpa16(smem_u32(vbuf + r * F2LD + sg * 8),
              Vm + (size_t)(brow0 + r) * Ec + coff + sg * 8);
    }
    CP_COMMIT();
}

__global__ __launch_bounds__(256) void flash_fused(
    const __half* __restrict__ Q, const __half* __restrict__ Km,
    const __half* __restrict__ Vm, const float* __restrict__ gw,
    __half* __restrict__ ctx)
{
    extern __shared__ __align__(16) __half smh[];
    __half* Qs = smh;                  // 64*136 (both heads' cols)
    __half* KV0 = Qs + 64 * F2LD;      // 2 stages of (K 64x136 + V 64x136)

    const int qtile = gridDim.x - 1 - blockIdx.x;   // longest CTAs first
    const int h = blockIdx.y;
    const int b = blockIdx.z;
    const int tid = threadIdx.x;
    const int wid = tid >> 5;
    const int lane = tid & 31;
    const int g = lane >> 2;
    const int tig = lane & 3;
    const int half = wid >> 2;         // 0 -> h2=2h, 1 -> h2=2h+1
    const int q4 = wid & 3;            // row-quad within half
    const int qm0 = qtile * 64;
    const int coff = h * 128;          // Q/K pair cols, V cols
    const int hoff = half * 64;        // this warp's Q/K sub-cols
    const int ntiles = qtile + 1;

    const int a_lrow = lane & 15;
    const int a_lcol = (lane >> 4) * 8;
    const int b_lrow = (lane & 7) + ((lane >> 4) << 3);
    const int b_lcol = ((lane >> 3) & 1) * 8;
    const int v_lrow = (lane & 7) + ((lane >> 3) & 1) * 8;
    const int v_lcol = ((lane >> 4) & 1) * 8;

    // ---- load Q tile (64 rows x 128 cols) ----
#pragma unroll
    for (int it = 0; it < 4; it++) {
        const int idx = tid + 256 * it;
        const int r = idx >> 4, sg = idx & 15;
        *(uint4*)(Qs + r * F2LD + sg * 8) =
            *(const uint4*)(Q + (size_t)(b * Tc + qm0 + r) * Ec + coff + sg * 8);
    }
    __syncthreads();

    // ---- Q fragments (this warp's head half) ----
    uint32_t qfr[4][4];
    {
        const uint32_t qb = smem_u32(Qs) +
            (uint32_t)(((q4 * 16 + a_lrow) * F2LD + hoff + a_lcol) * 2);
#pragma unroll
        for (int kd = 0; kd < 4; kd++)
            LDSM_X4(qfr[kd], qb + (uint32_t)(kd * 32));
    }

    float oacc[16][4];
#pragma unroll
    for (int j = 0; j < 16; j++)
#pragma unroll
        for (int r = 0; r < 4; r++) oacc[j][r] = 0.f;
    float mrow0 = -1e30f, mrow1 = -1e30f;
    float lrow0 = 0.f, lrow1 = 0.f;
    const int rowa = qm0 + q4 * 16 + g;

    ff_load_kv(KV0, Km, Vm, b * Tc, coff, tid);

    for (int kt = 0; kt < ntiles; kt++) {
        CP_WAIT(0);
        __syncthreads();
        if (kt + 1 < ntiles)
            ff_load_kv(KV0 + ((kt + 1) & 1) * KV2_STAGE, Km, Vm,
                       b * Tc + (kt + 1) * 64, coff, tid);

        const __half* Kbuf = KV0 + (kt & 1) * KV2_STAGE;
        const __half* Vbuf = Kbuf + 64 * F2LD;
        const uint32_t ksb = smem_u32(Kbuf) +
            (uint32_t)((b_lrow * F2LD + hoff + b_lcol) * 2);
        const uint32_t vsb = smem_u32(Vbuf) + (uint32_t)((v_lrow * F2LD + v_lcol) * 2);

        // ---- S = Q @ K^T ----
        float sacc[8][4];
#pragma unroll
        for (int j = 0; j < 8; j++)
#pragma unroll
            for (int r = 0; r < 4; r++) sacc[j][r] = 0.f;
#pragma unroll
        for (int kd = 0; kd < 4; kd++) {
#pragma unroll
            for (int jp = 0; jp < 4; jp++) {
                uint32_t bl[4];
                LDSM_X4(bl, ksb + (uint32_t)((jp * 16 * F2LD) * 2 + kd * 32));
                mma_f16(sacc[2 * jp], qfr[kd], bl);
                mma_f16(sacc[2 * jp + 1], qfr[kd], bl + 2);
            }
        }

        // ---- causal mask ----
        if (kt * 64 + 63 > rowa) {
#pragma unroll
            for (int j = 0; j < 8; j++) {
                const int colb = kt * 64 + j * 8 + 2 * tig;
                if (colb > rowa) sacc[j][0] = -1e30f;
                if (colb + 1 > rowa) sacc[j][1] = -1e30f;
                if (colb > rowa + 8) sacc[j][2] = -1e30f;
                if (colb + 1 > rowa + 8) sacc[j][3] = -1e30f;
            }
        }

        // ---- warp-local online softmax ----
        float m0 = -1e30f, m1 = -1e30f;
#pragma unroll
        for (int j = 0; j < 8; j++) {
            m0 = fmaxf(m0, fmaxf(sacc[j][0], sacc[j][1]));
            m1 = fmaxf(m1, fmaxf(sacc[j][2], sacc[j][3]));
        }
#pragma unroll
        for (int off = 1; off <= 2; off <<= 1) {
            m0 = fmaxf(m0, __shfl_xor_sync(0xffffffffu, m0, off));
            m1 = fmaxf(m1, __shfl_xor_sync(0xffffffffu, m1, off));
        }
        const float mn0 = fmaxf(mrow0, m0);
        const float mn1 = fmaxf(mrow1, m1);
        const float al0 = __expf(mrow0 - mn0);
        const float al1 = __expf(mrow1 - mn1);
        mrow0 = mn0; mrow1 = mn1;

        float s0 = 0.f, s1 = 0.f;
#pragma unroll
        for (int j = 0; j < 8; j++) {
            sacc[j][0] = __expf(sacc[j][0] - mn0);
            sacc[j][1] = __expf(sacc[j][1] - mn0);
            sacc[j][2] = __expf(sacc[j][2] - mn1);
            sacc[j][3] = __expf(sacc[j][3] - mn1);
            s0 += sacc[j][0] + sacc[j][1];
            s1 += sacc[j][2] + sacc[j][3];
        }
#pragma unroll
        for (int off = 1; off <= 2; off <<= 1) {
            s0 += __shfl_xor_sync(0xffffffffu, s0, off);
            s1 += __shfl_xor_sync(0xffffffffu, s1, off);
        }
        lrow0 = lrow0 * al0 + s0;
        lrow1 = lrow1 * al1 + s1;
#pragma unroll
        for (int j = 0; j < 16; j++) {
            oacc[j][0] *= al0; oacc[j][1] *= al0;
            oacc[j][2] *= al1; oacc[j][3] *= al1;
        }

        // ---- O += P @ V ----
#pragma unroll
        for (int kn = 0; kn < 4; kn++) {
            uint32_t aP[4];
            aP[0] = pack_h2(sacc[2 * kn][0], sacc[2 * kn][1]);
            aP[1] = pack_h2(sacc[2 * kn][2], sacc[2 * kn][3]);
            aP[2] = pack_h2(sacc[2 * kn + 1][0], sacc[2 * kn + 1][1]);
            aP[3] = pack_h2(sacc[2 * kn + 1][2], sacc[2 * kn + 1][3]);
#pragma unroll
            for (int jp = 0; jp < 8; jp++) {
                uint32_t vl[4];
                LDSM_X4_T(vl, vsb + (uint32_t)((kn * 16 * F2LD + jp * 16) * 2));
                mma_f16(oacc[2 * jp], aP, vl);
                mma_f16(oacc[2 * jp + 1], aP, vl + 2);
            }
        }
    }

    // ---- fused epilogue: combine + RMSNorm + ctx write ----
    const float inv0 = 1.f / lrow0;
    const float inv1 = 1.f / lrow1;
    __syncthreads();                       // everyone done with KV smem
    float* X2 = (float*)KV0;               // [64][X2LD] fp32 exchange buffer

    if (half == 1) {
        // stash normalized O2
#pragma unroll
        for (int j = 0; j < 16; j++) {
            const int col = j * 8 + 2 * tig;
            float* r0 = X2 + (q4 * 16 + g) * X2LD + col;
            float* r1 = X2 + (q4 * 16 + g + 8) * X2LD + col;
            r0[0] = oacc[j][0] * inv0; r0[1] = oacc[j][1] * inv0;
            r1[0] = oacc[j][2] * inv1; r1[1] = oacc[j][3] * inv1;
        }
    }
    __syncthreads();
    if (half == 0) {
        const float lam = g_lam;
        const float LI = 0.8f - 0.6f * expf(-3.6f);
        float ss0 = 0.f, ss1 = 0.f;
#pragma unroll
        for (int j = 0; j < 16; j++) {
            const int col = j * 8 + 2 * tig;
            const float* r0 = X2 + (q4 * 16 + g) * X2LD + col;
            const float* r1 = X2 + (q4 * 16 + g + 8) * X2LD + col;
            oacc[j][0] = oacc[j][0] * inv0 - lam * r0[0];
            oacc[j][1] = oacc[j][1] * inv0 - lam * r0[1];
            oacc[j][2] = oacc[j][2] * inv1 - lam * r1[0];
            oacc[j][3] = oacc[j][3] * inv1 - lam * r1[1];
            ss0 += oacc[j][0] * oacc[j][0] + oacc[j][1] * oacc[j][1];
            ss1 += oacc[j][2] * oacc[j][2] + oacc[j][3] * oacc[j][3];
        }
#pragma unroll
        for (int off = 1; off <= 2; off <<= 1) {
            ss0 += __shfl_xor_sync(0xffffffffu, ss0, off);
            ss1 += __shfl_xor_sync(0xffffffffu, ss1, off);
        }
        const float sc0 = rsqrtf(ss0 * (1.f / 128.f) + 1e-5f) * (1.f - LI);
        const float sc1 = rsqrtf(ss1 * (1.f / 128.f) + 1e-5f) * (1.f - LI);
        const int t0 = qm0 + q4 * 16 + g;
        __half* d0 = ctx + (size_t)(b * Tc + t0) * Ec + coff;
        __half* d1 = ctx + (size_t)(b * Tc + t0 + 8) * Ec + coff;
#pragma unroll
        for (int j = 0; j < 16; j++) {
            const int col = j * 8 + 2 * tig;
            float2 gv = *(const float2*)(gw + col);
            *(__half2*)(d0 + col) =
                __floats2half2_rn(oacc[j][0] * sc0 * gv.x, oacc[j][1] * sc0 * gv.y);
            *(__half2*)(d1 + col) =
                __floats2half2_rn(oacc[j][2] * sc1 * gv.x, oacc[j][3] * sc1 * gv.y);
        }
    }
}

// ---------------------------------------------------------------------------
// Host launcher
// ---------------------------------------------------------------------------
extern "C" void kernel_launch(void* const* d_in, const int* in_sizes, int n_in,
                              void* d_out, int out_size)
{
    (void)in_sizes; (void)n_in; (void)out_size;

    const float* query = (const float*)d_in[0];
    const float* Wq = (const float*)d_in[1];
    const float* Wk = (const float*)d_in[2];
    const float* Wv = (const float*)d_in[3];
    const float* Wo = (const float*)d_in[4];
    const float* lq1 = (const float*)d_in[5];
    const float* lk1 = (const float*)d_in[6];
    const float* lq2 = (const float*)d_in[7];
    const float* lk2 = (const float*)d_in[8];
    const float* gw = (const float*)d_in[9];
    float* out = (float*)d_out;

    __half *pQ, *pK, *pV, *pC, *pXh, *pWh;
    cudaGetSymbolAddress((void**)&pQ, g_Q);
    cudaGetSymbolAddress((void**)&pK, g_K);
    cudaGetSymbolAddress((void**)&pV, g_V);
    cudaGetSymbolAddress((void**)&pC, g_ctx);
    cudaGetSymbolAddress((void**)&pXh, g_Xh);
    cudaGetSymbolAddress((void**)&pWh, g_Wh);

    cudaFuncSetAttribute(gemm_qkv, cudaFuncAttributeMaxDynamicSharedMemorySize, GSMEM_BYTES);
    cudaFuncSetAttribute(gemm_wo, cudaFuncAttributeMaxDynamicSharedMemorySize, GSMEM_BYTES);
    cudaFuncSetAttribute(flash_fused, cudaFuncAttributeMaxDynamicSharedMemorySize, FF_SMEM_BYTES);

    const int NW4 = (Ec * Ec) / 4;
    const int NX4 = (MTOT * Ec) / 4;
    const int RB = 256;

    // conversions up front
    cvt_f2h_kernel<<<(NX4 + RB - 1) / RB, RB>>>(query, pXh, NX4);
    cvt_w4_kernel<<<dim3(NW4 / RB, 4), RB>>>(Wq, Wk, Wv, Wo, pWh);
    lambda_kernel<<<1, 1>>>(lq1, lk1, lq2, lk2);

    // fused Q/K/V projections (BK=64, 3-stage)
    gemm_qkv<<<dim3(Ec / BN, MTOT / BM, 3), GTHREADS, GSMEM_BYTES>>>(pXh, pWh, pQ, pK, pV);

    // fused flash attention + combine + RMSNorm -> ctx (fp16)
    flash_fused<<<dim3(Tc / 64, Hc, Bc), 256, FF_SMEM_BYTES>>>(pQ, pK, pV, gw, pC);

    // output projection (fp32 out)
    gemm_wo<<<dim3(Ec / BN, MTOT / BM), GTHREADS, GSMEM_BYTES>>>(pC, pWh + 3 * (size_t)Ec * Ec, out);
}